// round 4
// baseline (speedup 1.0000x reference)
#include <cuda_runtime.h>
#include <cuda_bf16.h>
#include <math.h>
#include <cstdint>

// ---------------- problem constants ----------------
#define NROI 128
#define CCH  256
#define ECH  256
#define M_GEMM (NROI*9)      // 1152
#define K_GEMM (CCH*9)       // 2304
#define N_GEMM ECH           // 256

#define SPLITK 8
#define KSLICE (K_GEMM/SPLITK)   // 288
#define BK     32
#define NSTAGE (KSLICE/BK)       // 9
#define SROW   36                // padded smem row stride (floats)

// ---------------- device scratch (no runtime alloc allowed) ----------------
__device__ __align__(256) float g_R[(size_t)NROI * CCH * 9];               // 1.18 MB
__device__ __align__(256) float g_hpart[(size_t)SPLITK * M_GEMM * N_GEMM]; // 9.4 MB
__device__ __align__(256) float g_h[(size_t)M_GEMM * N_GEMM];              // 1.18 MB

__device__ __forceinline__ float f2tf32(float x) {
    float r;
    asm("cvt.rna.tf32.f32 %0, %1;" : "=f"(r) : "f"(x));
    return r;
}

__device__ __forceinline__ void mma_tf32(float c[4],
                                         uint32_t a0, uint32_t a1, uint32_t a2, uint32_t a3,
                                         uint32_t b0, uint32_t b1) {
    asm volatile(
        "mma.sync.aligned.m16n8k8.row.col.f32.tf32.tf32.f32 "
        "{%0,%1,%2,%3}, {%4,%5,%6,%7}, {%8,%9}, {%0,%1,%2,%3};"
        : "+f"(c[0]), "+f"(c[1]), "+f"(c[2]), "+f"(c[3])
        : "r"(a0), "r"(a1), "r"(a2), "r"(a3), "r"(b0), "r"(b1));
}

// ---------------------------------------------------------------------------
// K1: ROI-align -> compact R[n][c][9].  grid (NROI, 4) x 64 threads.
// ---------------------------------------------------------------------------
__global__ void __launch_bounds__(64) k_roi(
    const float* __restrict__ fm, const float* __restrict__ boxes,
    const int* __restrict__ batch_idx, const int* __restrict__ level_idx)
{
    const int n = blockIdx.x;
    const int c = blockIdx.y * 64 + threadIdx.x;

    const int lvl = level_idx[n];
    const int b   = batch_idx[n];
    const float stride = (float)(8 << lvl);
    const float hv     = (float)(128 >> lvl);
    const float scale  = 1.0f / stride;

    const float x1 = boxes[n*4+0] * scale;
    const float y1 = boxes[n*4+1] * scale;
    const float x2 = boxes[n*4+2] * scale;
    const float y2 = boxes[n*4+3] * scale;
    const float roi_w = fmaxf(x2 - x1, 1.0f);
    const float roi_h = fmaxf(y2 - y1, 1.0f);

    const float* __restrict__ plane =
        fm + ((size_t)(lvl*2 + b) * CCH + c) * 128 * 128;
    const int hi = (int)(hv - 1.0f);

    float* __restrict__ r = g_R + ((size_t)n * CCH + c) * 9;

    #pragma unroll
    for (int py = 0; py < 3; py++) {
        const float offy = ((float)py + 0.5f) / 3.0f;
        const float y = y1 + offy * roi_h;
        #pragma unroll
        for (int px = 0; px < 3; px++) {
            const float offx = ((float)px + 0.5f) / 3.0f;
            const float x = x1 + offx * roi_w;
            const bool valid = (y > -1.0f) && (y < hv) && (x > -1.0f) && (x < hv);
            const float yc = fminf(fmaxf(y, 0.0f), hv - 1.0f);
            const float xc = fminf(fmaxf(x, 0.0f), hv - 1.0f);
            const int y0 = (int)floorf(yc);
            const int x0 = (int)floorf(xc);
            const int y1i = min(y0 + 1, hi);
            const int x1i = min(x0 + 1, hi);
            const float ly = yc - (float)y0;
            const float lx = xc - (float)x0;
            const float v00 = plane[y0 * 128 + x0];
            const float v01 = plane[y0 * 128 + x1i];
            const float v10 = plane[y1i * 128 + x0];
            const float v11 = plane[y1i * 128 + x1i];
            float val = (1.0f-ly)*(1.0f-lx)*v00 + (1.0f-ly)*lx*v01
                      + ly*(1.0f-lx)*v10 + ly*lx*v11;
            r[py*3 + px] = valid ? val : 0.0f;
        }
    }
}

// ---------------------------------------------------------------------------
// K2: 3xTF32 mma.sync GEMM with fused im2col A-gather from g_R.
// h[m,e] = sum_k A[m,k]*W[e,k].  grid (9, 2, 8) = 144 CTAs, 256 thr (8 warps 4x2).
// ---------------------------------------------------------------------------
__global__ void __launch_bounds__(256, 1) k_gemm_mma(const float* __restrict__ conv_w)
{
    __shared__ float As[2][128 * SROW];   // [hi/lo][row*36 + k]
    __shared__ float Bs[2][128 * SROW];

    const int tid  = threadIdx.x;
    const int wid  = tid >> 5;
    const int lane = tid & 31;
    const int warp_m = wid & 3;
    const int warp_n = wid >> 2;

    const int m0 = blockIdx.x * 128;
    const int n0 = blockIdx.y * 128;
    const int k0 = blockIdx.z * KSLICE;

    // B loader mapping (float4): idx = tid + q*256; row = idx>>3; col4 = idx&7
    const int lrow = tid >> 3;
    const int lcol = (tid & 7) * 4;

    float acc[2][8][4];
    #pragma unroll
    for (int i = 0; i < 2; i++)
        #pragma unroll
        for (int j = 0; j < 8; j++)
            #pragma unroll
            for (int q = 0; q < 4; q++) acc[i][j][q] = 0.0f;

    const float* __restrict__ Bbase = conv_w + (size_t)n0 * K_GEMM + k0;

    // A gather constants per thread: 16 elems, idx = tid + i*256; row = idx>>5, col = idx&31
    // row-dependent decode (same for all stages; k varies with stage)
    int a_n[16], a_py[16], a_px[16];
    #pragma unroll
    for (int i = 0; i < 16; i++) {
        const int idx = tid + i * 256;
        const int row = idx >> 5;
        const int m = m0 + row;
        const int n = m / 9;
        const int p = m - n * 9;
        a_n[i] = n;
        a_py[i] = p / 3;
        a_px[i] = p - (p / 3) * 3;
    }

    float4 rb[4];
    #pragma unroll
    for (int q = 0; q < 4; q++)
        rb[q] = *(const float4*)(Bbase + (size_t)(lrow + q * 32) * K_GEMM + lcol);

    for (int s = 0; s < NSTAGE; s++) {
        // --- A: gather im2col values from g_R, split hi/lo, store smem ---
        #pragma unroll
        for (int i = 0; i < 16; i++) {
            const int idx = tid + i * 256;
            const int row = idx >> 5;
            const int col = idx & 31;
            const int k = k0 + s * BK + col;
            const int c = k / 9;
            const int kk = k - c * 9;
            const int ky = kk / 3;
            const int kx = kk - ky * 3;
            const int iy = a_py[i] + ky - 1;
            const int ix = a_px[i] + kx - 1;
            float v = 0.0f;
            if ((unsigned)iy < 3u && (unsigned)ix < 3u)
                v = g_R[((size_t)a_n[i] * CCH + c) * 9 + iy * 3 + ix];
            const float h = f2tf32(v);
            As[0][row * SROW + col] = h;
            As[1][row * SROW + col] = f2tf32(v - h);
        }
        // --- B: split hi/lo from prefetched regs, store smem ---
        #pragma unroll
        for (int q = 0; q < 4; q++) {
            const int row = lrow + q * 32;
            float4 h, l;
            h.x = f2tf32(rb[q].x); h.y = f2tf32(rb[q].y);
            h.z = f2tf32(rb[q].z); h.w = f2tf32(rb[q].w);
            l.x = f2tf32(rb[q].x - h.x); l.y = f2tf32(rb[q].y - h.y);
            l.z = f2tf32(rb[q].z - h.z); l.w = f2tf32(rb[q].w - h.w);
            *(float4*)(&Bs[0][row * SROW + lcol]) = h;
            *(float4*)(&Bs[1][row * SROW + lcol]) = l;
        }
        __syncthreads();

        // prefetch next B stage
        if (s + 1 < NSTAGE) {
            const int koff = (s + 1) * BK;
            #pragma unroll
            for (int q = 0; q < 4; q++)
                rb[q] = *(const float4*)(Bbase + (size_t)(lrow + q * 32) * K_GEMM + koff + lcol);
        }

        const int rbase = warp_m * 32 + (lane >> 2);
        const int nbase = warp_n * 64 + (lane >> 2);
        #pragma unroll
        for (int kc = 0; kc < 4; kc++) {
            const int kb = kc * 8 + (lane & 3);
            uint32_t ah[2][4], al[2][4];
            #pragma unroll
            for (int i = 0; i < 2; i++) {
                const int r = rbase + i * 16;
                ah[i][0] = __float_as_uint(As[0][r * SROW + kb]);
                ah[i][1] = __float_as_uint(As[0][(r + 8) * SROW + kb]);
                ah[i][2] = __float_as_uint(As[0][r * SROW + kb + 4]);
                ah[i][3] = __float_as_uint(As[0][(r + 8) * SROW + kb + 4]);
                al[i][0] = __float_as_uint(As[1][r * SROW + kb]);
                al[i][1] = __float_as_uint(As[1][(r + 8) * SROW + kb]);
                al[i][2] = __float_as_uint(As[1][r * SROW + kb + 4]);
                al[i][3] = __float_as_uint(As[1][(r + 8) * SROW + kb + 4]);
            }
            #pragma unroll
            for (int j = 0; j < 8; j++) {
                const int nn = nbase + j * 8;
                const uint32_t bh0 = __float_as_uint(Bs[0][nn * SROW + kb]);
                const uint32_t bh1 = __float_as_uint(Bs[0][nn * SROW + kb + 4]);
                const uint32_t bl0 = __float_as_uint(Bs[1][nn * SROW + kb]);
                const uint32_t bl1 = __float_as_uint(Bs[1][nn * SROW + kb + 4]);
                #pragma unroll
                for (int i = 0; i < 2; i++) {
                    mma_tf32(acc[i][j], ah[i][0], ah[i][1], ah[i][2], ah[i][3], bh0, bh1);
                    mma_tf32(acc[i][j], ah[i][0], ah[i][1], ah[i][2], ah[i][3], bl0, bl1);
                    mma_tf32(acc[i][j], al[i][0], al[i][1], al[i][2], al[i][3], bh0, bh1);
                }
            }
        }
        __syncthreads();
    }

    // write split-K partials
    float* __restrict__ hp = g_hpart + (size_t)blockIdx.z * ((size_t)M_GEMM * N_GEMM);
    #pragma unroll
    for (int i = 0; i < 2; i++) {
        const int row = m0 + warp_m * 32 + i * 16 + (lane >> 2);
        #pragma unroll
        for (int j = 0; j < 8; j++) {
            const int col = n0 + warp_n * 64 + j * 8 + 2 * (lane & 3);
            *(float2*)(hp + (size_t)row * N_GEMM + col) =
                make_float2(acc[i][j][0], acc[i][j][1]);
            *(float2*)(hp + (size_t)(row + 8) * N_GEMM + col) =
                make_float2(acc[i][j][2], acc[i][j][3]);
        }
    }
}

// ---------------------------------------------------------------------------
// K3a: streaming split-K reduce: g_h = sum_sp g_hpart[sp].  Fully coalesced.
// grid = M_GEMM*N_GEMM/4/256 = 288 blocks x 256 threads, float4 per thread.
// ---------------------------------------------------------------------------
__global__ void __launch_bounds__(256) k_reduce()
{
    const size_t i4 = (size_t)blockIdx.x * 256 + threadIdx.x;   // float4 index
    const float4* __restrict__ hp = (const float4*)g_hpart;
    const size_t stride4 = (size_t)M_GEMM * N_GEMM / 4;

    float4 s = hp[i4];
    #pragma unroll
    for (int sp = 1; sp < SPLITK; sp++) {
        const float4 v = hp[(size_t)sp * stride4 + i4];
        s.x += v.x; s.y += v.y; s.z += v.z; s.w += v.w;
    }
    ((float4*)g_h)[i4] = s;
}

// ---------------------------------------------------------------------------
// K3b: per-roi GN + relu + mean + GEMVs. grid = NROI x 256.
// ---------------------------------------------------------------------------
__global__ void __launch_bounds__(256) k_epilogue(
    const float* __restrict__ boxes,
    const float* __restrict__ gn_scale, const float* __restrict__ gn_bias,
    const float* __restrict__ head_w,   const float* __restrict__ head_b,
    const float* __restrict__ spat_w,   const float* __restrict__ spat_b,
    const float* __restrict__ sym_emb,
    const float* __restrict__ fuse_w,   const float* __restrict__ fuse_b,
    const int*   __restrict__ sym_ids,
    float* __restrict__ out)
{
    const int n = blockIdx.x;
    const int e = threadIdx.x;

    float hvp[9];
    #pragma unroll
    for (int p = 0; p < 9; p++)
        hvp[p] = g_h[(size_t)(n*9 + p) * N_GEMM + e];

    float lsum = 0.0f;
    #pragma unroll
    for (int p = 0; p < 9; p++) lsum += hvp[p];
    #pragma unroll
    for (int o = 16; o > 0; o >>= 1) lsum += __shfl_xor_sync(0xffffffffu, lsum, o);
    const float mean = lsum * (1.0f / 288.0f);

    float lsq = 0.0f;
    #pragma unroll
    for (int p = 0; p < 9; p++) { float d = hvp[p] - mean; lsq += d * d; }
    #pragma unroll
    for (int o = 16; o > 0; o >>= 1) lsq += __shfl_xor_sync(0xffffffffu, lsq, o);
    const float var = lsq * (1.0f / 288.0f);
    const float inv = rsqrtf(var + 1e-5f);

    const float sc = gn_scale[e];
    const float bi = gn_bias[e];
    float acc = 0.0f;
    #pragma unroll
    for (int p = 0; p < 9; p++)
        acc += fmaxf((hvp[p] - mean) * inv * sc + bi, 0.0f);
    const float sval = acc * (1.0f / 9.0f);

    __shared__ float sbuf[256];
    sbuf[e] = sval;
    __syncthreads();

    float ho = head_b[e];
    const float* __restrict__ hw = head_w + (size_t)e * 256;
    #pragma unroll 8
    for (int j = 0; j < 256; j += 4) {
        const float4 w = *(const float4*)(hw + j);
        ho += sbuf[j]   * w.x + sbuf[j+1] * w.y
            + sbuf[j+2] * w.z + sbuf[j+3] * w.w;
    }
    ho = fmaxf(ho, 0.0f);

    const float b0 = boxes[n*4+0], b1 = boxes[n*4+1], b2 = boxes[n*4+2], b3 = boxes[n*4+3];
    float sp = spat_b[e] + b0 * spat_w[e*4+0] + b1 * spat_w[e*4+1]
                         + b2 * spat_w[e*4+2] + b3 * spat_w[e*4+3];
    sp = fmaxf(sp, 0.0f);

    const int sym = sym_ids[n];
    const float fused = ho + sp + sym_emb[sym * 256 + e];

    __syncthreads();
    sbuf[e] = fused;
    __syncthreads();

    float o = fuse_b[sym * 256 + e];
    const float* __restrict__ fw = fuse_w + ((size_t)sym * 256 + e) * 256;
    #pragma unroll 8
    for (int j = 0; j < 256; j += 4) {
        const float4 w = *(const float4*)(fw + j);
        o += sbuf[j]   * w.x + sbuf[j+1] * w.y
           + sbuf[j+2] * w.z + sbuf[j+3] * w.w;
    }
    out[(size_t)n * 256 + e] = fmaxf(o, 0.0f);
}

// ---------------------------------------------------------------------------
extern "C" void kernel_launch(void* const* d_in, const int* in_sizes, int n_in,
                              void* d_out, int out_size)
{
    const float* fm        = (const float*)d_in[0];
    const float* boxes     = (const float*)d_in[1];
    const float* conv_w    = (const float*)d_in[2];
    const float* gn_scale  = (const float*)d_in[3];
    const float* gn_bias   = (const float*)d_in[4];
    const float* head_w    = (const float*)d_in[5];
    const float* head_b    = (const float*)d_in[6];
    const float* spat_w    = (const float*)d_in[7];
    const float* spat_b    = (const float*)d_in[8];
    const float* sym_emb   = (const float*)d_in[9];
    const float* fuse_w    = (const float*)d_in[10];
    const float* fuse_b    = (const float*)d_in[11];
    const int*   batch_idx = (const int*)d_in[12];
    const int*   level_idx = (const int*)d_in[13];
    const int*   sym_ids   = (const int*)d_in[14];
    float* out = (float*)d_out;

    dim3 g1(NROI, 4);
    k_roi<<<g1, 64>>>(fm, boxes, batch_idx, level_idx);

    dim3 g2(M_GEMM / 128, N_GEMM / 128, SPLITK);   // (9, 2, 8) = 144 CTAs
    k_gemm_mma<<<g2, 256>>>(conv_w);

    k_reduce<<<(M_GEMM * N_GEMM / 4) / 256, 256>>>();

    k_epilogue<<<NROI, 256>>>(boxes, gn_scale, gn_bias, head_w, head_b,
                              spat_w, spat_b, sym_emb, fuse_w, fuse_b,
                              sym_ids, out);
}

// round 5
// speedup vs baseline: 1.2589x; 1.2589x over previous
#include <cuda_runtime.h>
#include <cuda_bf16.h>
#include <math.h>
#include <cstdint>

// ---------------- problem constants ----------------
#define NROI 128
#define CCH  256
#define ECH  256
#define M_GEMM (NROI*9)      // 1152
#define K_GEMM (CCH*9)       // 2304
#define N_GEMM ECH           // 256

#define SPLITK 8
#define KSLICE (K_GEMM/SPLITK)   // 288
#define BK     32
#define NSTAGE (KSLICE/BK)       // 9
#define SROW   36                // padded smem row stride (floats)

// ---------------- device scratch (no runtime alloc allowed) ----------------
__device__ __align__(256) float g_R[(size_t)NROI * CCH * 9];               // 1.18 MB
__device__ __align__(256) float g_hpart[(size_t)SPLITK * M_GEMM * N_GEMM]; // 9.4 MB
__device__ __align__(256) float g_h[(size_t)M_GEMM * N_GEMM];              // 1.18 MB

__device__ __forceinline__ float f2tf32(float x) {
    float r;
    asm("cvt.rna.tf32.f32 %0, %1;" : "=f"(r) : "f"(x));
    return r;
}

__device__ __forceinline__ void mma_tf32(float c[4],
                                         uint32_t a0, uint32_t a1, uint32_t a2, uint32_t a3,
                                         uint32_t b0, uint32_t b1) {
    asm volatile(
        "mma.sync.aligned.m16n8k8.row.col.f32.tf32.tf32.f32 "
        "{%0,%1,%2,%3}, {%4,%5,%6,%7}, {%8,%9}, {%0,%1,%2,%3};"
        : "+f"(c[0]), "+f"(c[1]), "+f"(c[2]), "+f"(c[3])
        : "r"(a0), "r"(a1), "r"(a2), "r"(a3), "r"(b0), "r"(b1));
}

// ---------------------------------------------------------------------------
// K1: ROI-align -> compact R[n][c][9].  grid (NROI, 4) x 64 threads.
// ---------------------------------------------------------------------------
__global__ void __launch_bounds__(64) k_roi(
    const float* __restrict__ fm, const float* __restrict__ boxes,
    const int* __restrict__ batch_idx, const int* __restrict__ level_idx)
{
    const int n = blockIdx.x;
    const int c = blockIdx.y * 64 + threadIdx.x;

    const int lvl = level_idx[n];
    const int b   = batch_idx[n];
    const float stride = (float)(8 << lvl);
    const float hv     = (float)(128 >> lvl);
    const float scale  = 1.0f / stride;

    const float x1 = boxes[n*4+0] * scale;
    const float y1 = boxes[n*4+1] * scale;
    const float x2 = boxes[n*4+2] * scale;
    const float y2 = boxes[n*4+3] * scale;
    const float roi_w = fmaxf(x2 - x1, 1.0f);
    const float roi_h = fmaxf(y2 - y1, 1.0f);

    const float* __restrict__ plane =
        fm + ((size_t)(lvl*2 + b) * CCH + c) * 128 * 128;
    const int hi = (int)(hv - 1.0f);

    float* __restrict__ r = g_R + ((size_t)n * CCH + c) * 9;

    #pragma unroll
    for (int py = 0; py < 3; py++) {
        const float offy = ((float)py + 0.5f) / 3.0f;
        const float y = y1 + offy * roi_h;
        #pragma unroll
        for (int px = 0; px < 3; px++) {
            const float offx = ((float)px + 0.5f) / 3.0f;
            const float x = x1 + offx * roi_w;
            const bool valid = (y > -1.0f) && (y < hv) && (x > -1.0f) && (x < hv);
            const float yc = fminf(fmaxf(y, 0.0f), hv - 1.0f);
            const float xc = fminf(fmaxf(x, 0.0f), hv - 1.0f);
            const int y0 = (int)floorf(yc);
            const int x0 = (int)floorf(xc);
            const int y1i = min(y0 + 1, hi);
            const int x1i = min(x0 + 1, hi);
            const float ly = yc - (float)y0;
            const float lx = xc - (float)x0;
            const float v00 = plane[y0 * 128 + x0];
            const float v01 = plane[y0 * 128 + x1i];
            const float v10 = plane[y1i * 128 + x0];
            const float v11 = plane[y1i * 128 + x1i];
            float val = (1.0f-ly)*(1.0f-lx)*v00 + (1.0f-ly)*lx*v01
                      + ly*(1.0f-lx)*v10 + ly*lx*v11;
            r[py*3 + px] = valid ? val : 0.0f;
        }
    }
}

// ---------------------------------------------------------------------------
// K2: 3xTF32 mma.sync GEMM with fused im2col A-gather from g_R.
// ---------------------------------------------------------------------------
__global__ void __launch_bounds__(256, 1) k_gemm_mma(const float* __restrict__ conv_w)
{
    __shared__ float As[2][128 * SROW];
    __shared__ float Bs[2][128 * SROW];

    const int tid  = threadIdx.x;
    const int wid  = tid >> 5;
    const int lane = tid & 31;
    const int warp_m = wid & 3;
    const int warp_n = wid >> 2;

    const int m0 = blockIdx.x * 128;
    const int n0 = blockIdx.y * 128;
    const int k0 = blockIdx.z * KSLICE;

    const int lrow = tid >> 3;
    const int lcol = (tid & 7) * 4;

    float acc[2][8][4];
    #pragma unroll
    for (int i = 0; i < 2; i++)
        #pragma unroll
        for (int j = 0; j < 8; j++)
            #pragma unroll
            for (int q = 0; q < 4; q++) acc[i][j][q] = 0.0f;

    const float* __restrict__ Bbase = conv_w + (size_t)n0 * K_GEMM + k0;

    int a_n[16], a_py[16], a_px[16];
    #pragma unroll
    for (int i = 0; i < 16; i++) {
        const int idx = tid + i * 256;
        const int row = idx >> 5;
        const int m = m0 + row;
        const int n = m / 9;
        const int p = m - n * 9;
        a_n[i] = n;
        a_py[i] = p / 3;
        a_px[i] = p - (p / 3) * 3;
    }

    float4 rb[4];
    #pragma unroll
    for (int q = 0; q < 4; q++)
        rb[q] = *(const float4*)(Bbase + (size_t)(lrow + q * 32) * K_GEMM + lcol);

    for (int s = 0; s < NSTAGE; s++) {
        #pragma unroll
        for (int i = 0; i < 16; i++) {
            const int idx = tid + i * 256;
            const int row = idx >> 5;
            const int col = idx & 31;
            const int k = k0 + s * BK + col;
            const int c = k / 9;
            const int kk = k - c * 9;
            const int ky = kk / 3;
            const int kx = kk - ky * 3;
            const int iy = a_py[i] + ky - 1;
            const int ix = a_px[i] + kx - 1;
            float v = 0.0f;
            if ((unsigned)iy < 3u && (unsigned)ix < 3u)
                v = g_R[((size_t)a_n[i] * CCH + c) * 9 + iy * 3 + ix];
            const float h = f2tf32(v);
            As[0][row * SROW + col] = h;
            As[1][row * SROW + col] = f2tf32(v - h);
        }
        #pragma unroll
        for (int q = 0; q < 4; q++) {
            const int row = lrow + q * 32;
            float4 h, l;
            h.x = f2tf32(rb[q].x); h.y = f2tf32(rb[q].y);
            h.z = f2tf32(rb[q].z); h.w = f2tf32(rb[q].w);
            l.x = f2tf32(rb[q].x - h.x); l.y = f2tf32(rb[q].y - h.y);
            l.z = f2tf32(rb[q].z - h.z); l.w = f2tf32(rb[q].w - h.w);
            *(float4*)(&Bs[0][row * SROW + lcol]) = h;
            *(float4*)(&Bs[1][row * SROW + lcol]) = l;
        }
        __syncthreads();

        if (s + 1 < NSTAGE) {
            const int koff = (s + 1) * BK;
            #pragma unroll
            for (int q = 0; q < 4; q++)
                rb[q] = *(const float4*)(Bbase + (size_t)(lrow + q * 32) * K_GEMM + koff + lcol);
        }

        const int rbase = warp_m * 32 + (lane >> 2);
        const int nbase = warp_n * 64 + (lane >> 2);
        #pragma unroll
        for (int kc = 0; kc < 4; kc++) {
            const int kb = kc * 8 + (lane & 3);
            uint32_t ah[2][4], al[2][4];
            #pragma unroll
            for (int i = 0; i < 2; i++) {
                const int r = rbase + i * 16;
                ah[i][0] = __float_as_uint(As[0][r * SROW + kb]);
                ah[i][1] = __float_as_uint(As[0][(r + 8) * SROW + kb]);
                ah[i][2] = __float_as_uint(As[0][r * SROW + kb + 4]);
                ah[i][3] = __float_as_uint(As[0][(r + 8) * SROW + kb + 4]);
                al[i][0] = __float_as_uint(As[1][r * SROW + kb]);
                al[i][1] = __float_as_uint(As[1][(r + 8) * SROW + kb]);
                al[i][2] = __float_as_uint(As[1][r * SROW + kb + 4]);
                al[i][3] = __float_as_uint(As[1][(r + 8) * SROW + kb + 4]);
            }
            #pragma unroll
            for (int j = 0; j < 8; j++) {
                const int nn = nbase + j * 8;
                const uint32_t bh0 = __float_as_uint(Bs[0][nn * SROW + kb]);
                const uint32_t bh1 = __float_as_uint(Bs[0][nn * SROW + kb + 4]);
                const uint32_t bl0 = __float_as_uint(Bs[1][nn * SROW + kb]);
                const uint32_t bl1 = __float_as_uint(Bs[1][nn * SROW + kb + 4]);
                #pragma unroll
                for (int i = 0; i < 2; i++) {
                    mma_tf32(acc[i][j], ah[i][0], ah[i][1], ah[i][2], ah[i][3], bh0, bh1);
                    mma_tf32(acc[i][j], ah[i][0], ah[i][1], ah[i][2], ah[i][3], bl0, bl1);
                    mma_tf32(acc[i][j], al[i][0], al[i][1], al[i][2], al[i][3], bh0, bh1);
                }
            }
        }
        __syncthreads();
    }

    float* __restrict__ hp = g_hpart + (size_t)blockIdx.z * ((size_t)M_GEMM * N_GEMM);
    #pragma unroll
    for (int i = 0; i < 2; i++) {
        const int row = m0 + warp_m * 32 + i * 16 + (lane >> 2);
        #pragma unroll
        for (int j = 0; j < 8; j++) {
            const int col = n0 + warp_n * 64 + j * 8 + 2 * (lane & 3);
            *(float2*)(hp + (size_t)row * N_GEMM + col) =
                make_float2(acc[i][j][0], acc[i][j][1]);
            *(float2*)(hp + (size_t)(row + 8) * N_GEMM + col) =
                make_float2(acc[i][j][2], acc[i][j][3]);
        }
    }
}

// ---------------------------------------------------------------------------
// K3a: streaming split-K reduce: g_h = sum_sp g_hpart[sp].
// ---------------------------------------------------------------------------
__global__ void __launch_bounds__(256) k_reduce()
{
    const size_t i4 = (size_t)blockIdx.x * 256 + threadIdx.x;
    const float4* __restrict__ hp = (const float4*)g_hpart;
    const size_t stride4 = (size_t)M_GEMM * N_GEMM / 4;

    float4 s = hp[i4];
    #pragma unroll
    for (int sp = 1; sp < SPLITK; sp++) {
        const float4 v = hp[(size_t)sp * stride4 + i4];
        s.x += v.x; s.y += v.y; s.z += v.z; s.w += v.w;
    }
    ((float4*)g_h)[i4] = s;
}

// ---------------------------------------------------------------------------
// K3b: per-roi epilogue, 1024 threads. Warp-cooperative GEMVs.
// ---------------------------------------------------------------------------
__global__ void __launch_bounds__(1024) k_epilogue(
    const float* __restrict__ boxes,
    const float* __restrict__ gn_scale, const float* __restrict__ gn_bias,
    const float* __restrict__ head_w,   const float* __restrict__ head_b,
    const float* __restrict__ spat_w,   const float* __restrict__ spat_b,
    const float* __restrict__ sym_emb,
    const float* __restrict__ fuse_w,   const float* __restrict__ fuse_b,
    const int*   __restrict__ sym_ids,
    float* __restrict__ out)
{
    const int n   = blockIdx.x;
    const int tid = threadIdx.x;
    const int w   = tid >> 5;     // 0..31
    const int l   = tid & 31;

    __shared__ float sbuf[256];   // GN-pooled vector s[e]
    __shared__ float fbuf[256];   // fused vector
    __shared__ float hobuf[256];  // head GEMV raw outputs

    const int sym = sym_ids[n];

    // ---- Phase 1: GN + relu + spatial mean (threads 0..255; warp == group) ----
    if (tid < 256) {
        const int e = tid;
        float hvp[9];
        #pragma unroll
        for (int p = 0; p < 9; p++)
            hvp[p] = g_h[(size_t)(n*9 + p) * N_GEMM + e];

        float lsum = 0.0f;
        #pragma unroll
        for (int p = 0; p < 9; p++) lsum += hvp[p];
        #pragma unroll
        for (int o = 16; o > 0; o >>= 1) lsum += __shfl_xor_sync(0xffffffffu, lsum, o);
        const float mean = lsum * (1.0f / 288.0f);

        float lsq = 0.0f;
        #pragma unroll
        for (int p = 0; p < 9; p++) { float d = hvp[p] - mean; lsq += d * d; }
        #pragma unroll
        for (int o = 16; o > 0; o >>= 1) lsq += __shfl_xor_sync(0xffffffffu, lsq, o);
        const float inv = rsqrtf(lsq * (1.0f / 288.0f) + 1e-5f);

        const float sc = gn_scale[e];
        const float bi = gn_bias[e];
        float acc = 0.0f;
        #pragma unroll
        for (int p = 0; p < 9; p++)
            acc += fmaxf((hvp[p] - mean) * inv * sc + bi, 0.0f);
        sbuf[e] = acc * (1.0f / 9.0f);
    }
    __syncthreads();

    // ---- Phase 2: head GEMV (warp w -> outputs w*8..w*8+7) ----
    {
        float sv[8];
        #pragma unroll
        for (int t = 0; t < 8; t++) sv[t] = sbuf[l + 32 * t];

        float a[8];
        #pragma unroll
        for (int o = 0; o < 8; o++) a[o] = 0.0f;

        const float* __restrict__ hw = head_w + (size_t)(w * 8) * 256 + l;
        #pragma unroll
        for (int o = 0; o < 8; o++) {
            #pragma unroll
            for (int t = 0; t < 8; t++)
                a[o] = fmaf(sv[t], hw[o * 256 + 32 * t], a[o]);
        }
        #pragma unroll
        for (int o = 0; o < 8; o++) {
            #pragma unroll
            for (int off = 16; off > 0; off >>= 1)
                a[o] += __shfl_xor_sync(0xffffffffu, a[o], off);
        }
        if (l < 8) {
            const int e = w * 8 + l;
            // lane l holds a[l]'s fully-reduced value in every lane; pick per-lane
            float v = a[0];
            #pragma unroll
            for (int o = 1; o < 8; o++) v = (l == o) ? a[o] : v;
            hobuf[e] = v + head_b[e];
        }
    }
    __syncthreads();

    // ---- fused vector (threads 0..255) ----
    if (tid < 256) {
        const int e = tid;
        const float ho = fmaxf(hobuf[e], 0.0f);
        const float b0 = boxes[n*4+0], b1 = boxes[n*4+1],
                    b2 = boxes[n*4+2], b3 = boxes[n*4+3];
        float sp = spat_b[e] + b0 * spat_w[e*4+0] + b1 * spat_w[e*4+1]
                             + b2 * spat_w[e*4+2] + b3 * spat_w[e*4+3];
        sp = fmaxf(sp, 0.0f);
        fbuf[e] = ho + sp + sym_emb[sym * 256 + e];
    }
    __syncthreads();

    // ---- Phase 3: fuse GEMV (warp w -> outputs w*8..w*8+7) ----
    {
        float fv[8];
        #pragma unroll
        for (int t = 0; t < 8; t++) fv[t] = fbuf[l + 32 * t];

        float a[8];
        #pragma unroll
        for (int o = 0; o < 8; o++) a[o] = 0.0f;

        const float* __restrict__ fw =
            fuse_w + ((size_t)sym * 256 + (size_t)(w * 8)) * 256 + l;
        #pragma unroll
        for (int o = 0; o < 8; o++) {
            #pragma unroll
            for (int t = 0; t < 8; t++)
                a[o] = fmaf(fv[t], fw[o * 256 + 32 * t], a[o]);
        }
        #pragma unroll
        for (int o = 0; o < 8; o++) {
            #pragma unroll
            for (int off = 16; off > 0; off >>= 1)
                a[o] += __shfl_xor_sync(0xffffffffu, a[o], off);
        }
        if (l < 8) {
            const int e = w * 8 + l;
            float v = a[0];
            #pragma unroll
            for (int o = 1; o < 8; o++) v = (l == o) ? a[o] : v;
            out[(size_t)n * 256 + e] = fmaxf(v + fuse_b[sym * 256 + e], 0.0f);
        }
    }
}

// ---------------------------------------------------------------------------
extern "C" void kernel_launch(void* const* d_in, const int* in_sizes, int n_in,
                              void* d_out, int out_size)
{
    const float* fm        = (const float*)d_in[0];
    const float* boxes     = (const float*)d_in[1];
    const float* conv_w    = (const float*)d_in[2];
    const float* gn_scale  = (const float*)d_in[3];
    const float* gn_bias   = (const float*)d_in[4];
    const float* head_w    = (const float*)d_in[5];
    const float* head_b    = (const float*)d_in[6];
    const float* spat_w    = (const float*)d_in[7];
    const float* spat_b    = (const float*)d_in[8];
    const float* sym_emb   = (const float*)d_in[9];
    const float* fuse_w    = (const float*)d_in[10];
    const float* fuse_b    = (const float*)d_in[11];
    const int*   batch_idx = (const int*)d_in[12];
    const int*   level_idx = (const int*)d_in[13];
    const int*   sym_ids   = (const int*)d_in[14];
    float* out = (float*)d_out;

    dim3 g1(NROI, 4);
    k_roi<<<g1, 64>>>(fm, boxes, batch_idx, level_idx);

    dim3 g2(M_GEMM / 128, N_GEMM / 128, SPLITK);   // (9, 2, 8) = 144 CTAs
    k_gemm_mma<<<g2, 256>>>(conv_w);

    k_reduce<<<(M_GEMM * N_GEMM / 4) / 256, 256>>>();

    k_epilogue<<<NROI, 1024>>>(boxes, gn_scale, gn_bias, head_w, head_b,
                               spat_w, spat_b, sym_emb, fuse_w, fuse_b,
                               sym_ids, out);
}

// round 6
// speedup vs baseline: 1.3147x; 1.0444x over previous
#include <cuda_runtime.h>
#include <cuda_bf16.h>
#include <math.h>
#include <cstdint>

// ---------------- problem constants ----------------
#define NROI 128
#define CCH  256
#define ECH  256
#define M_GEMM (NROI*9)      // 1152
#define K_GEMM (CCH*9)       // 2304
#define N_GEMM ECH           // 256

#define SPLITK 8
#define KSLICE (K_GEMM/SPLITK)   // 288
#define BK     32
#define NSTAGE (KSLICE/BK)       // 9
#define SROW   36                // padded smem row stride (floats)
#define TILE_F (128*SROW)        // floats per tile array
#define GEMM_SMEM_BYTES (2 * 4 * TILE_F * 4)   // 147456

// ---------------- device scratch (no runtime alloc allowed) ----------------
__device__ __align__(256) float g_R[(size_t)NROI * CCH * 9];               // 1.18 MB
__device__ __align__(256) float g_hpart[(size_t)SPLITK * M_GEMM * N_GEMM]; // 9.4 MB
__device__ __align__(256) float g_h[(size_t)M_GEMM * N_GEMM];              // 1.18 MB

__device__ __forceinline__ float f2tf32(float x) {
    float r;
    asm("cvt.rna.tf32.f32 %0, %1;" : "=f"(r) : "f"(x));
    return r;
}

__device__ __forceinline__ void mma_tf32(float c[4],
                                         uint32_t a0, uint32_t a1, uint32_t a2, uint32_t a3,
                                         uint32_t b0, uint32_t b1) {
    asm volatile(
        "mma.sync.aligned.m16n8k8.row.col.f32.tf32.tf32.f32 "
        "{%0,%1,%2,%3}, {%4,%5,%6,%7}, {%8,%9}, {%0,%1,%2,%3};"
        : "+f"(c[0]), "+f"(c[1]), "+f"(c[2]), "+f"(c[3])
        : "r"(a0), "r"(a1), "r"(a2), "r"(a3), "r"(b0), "r"(b1));
}

// ---------------------------------------------------------------------------
// K1: ROI-align -> compact R[n][c][9].  grid (NROI, 4) x 64 threads.
// ---------------------------------------------------------------------------
__global__ void __launch_bounds__(64) k_roi(
    const float* __restrict__ fm, const float* __restrict__ boxes,
    const int* __restrict__ batch_idx, const int* __restrict__ level_idx)
{
    const int n = blockIdx.x;
    const int c = blockIdx.y * 64 + threadIdx.x;

    const int lvl = level_idx[n];
    const int b   = batch_idx[n];
    const float stride = (float)(8 << lvl);
    const float hv     = (float)(128 >> lvl);
    const float scale  = 1.0f / stride;

    const float x1 = boxes[n*4+0] * scale;
    const float y1 = boxes[n*4+1] * scale;
    const float x2 = boxes[n*4+2] * scale;
    const float y2 = boxes[n*4+3] * scale;
    const float roi_w = fmaxf(x2 - x1, 1.0f);
    const float roi_h = fmaxf(y2 - y1, 1.0f);

    const float* __restrict__ plane =
        fm + ((size_t)(lvl*2 + b) * CCH + c) * 128 * 128;
    const int hi = (int)(hv - 1.0f);

    float* __restrict__ r = g_R + ((size_t)n * CCH + c) * 9;

    #pragma unroll
    for (int py = 0; py < 3; py++) {
        const float offy = ((float)py + 0.5f) / 3.0f;
        const float y = y1 + offy * roi_h;
        #pragma unroll
        for (int px = 0; px < 3; px++) {
            const float offx = ((float)px + 0.5f) / 3.0f;
            const float x = x1 + offx * roi_w;
            const bool valid = (y > -1.0f) && (y < hv) && (x > -1.0f) && (x < hv);
            const float yc = fminf(fmaxf(y, 0.0f), hv - 1.0f);
            const float xc = fminf(fmaxf(x, 0.0f), hv - 1.0f);
            const int y0 = (int)floorf(yc);
            const int x0 = (int)floorf(xc);
            const int y1i = min(y0 + 1, hi);
            const int x1i = min(x0 + 1, hi);
            const float ly = yc - (float)y0;
            const float lx = xc - (float)x0;
            const float v00 = plane[y0 * 128 + x0];
            const float v01 = plane[y0 * 128 + x1i];
            const float v10 = plane[y1i * 128 + x0];
            const float v11 = plane[y1i * 128 + x1i];
            float val = (1.0f-ly)*(1.0f-lx)*v00 + (1.0f-ly)*lx*v01
                      + ly*(1.0f-lx)*v10 + ly*lx*v11;
            r[py*3 + px] = valid ? val : 0.0f;
        }
    }
}

// ---------------------------------------------------------------------------
// K2: 3xTF32 mma.sync GEMM, fused im2col A-gather, double-buffered smem.
// grid (9, 2, 8) = 144 CTAs, 256 thr (8 warps 4x2).
// ---------------------------------------------------------------------------
__global__ void __launch_bounds__(256, 1) k_gemm_mma(const float* __restrict__ conv_w)
{
    extern __shared__ float smx[];   // [2 buffers][Ah|Al|Bh|Bl][128*SROW]

    const int tid  = threadIdx.x;
    const int wid  = tid >> 5;
    const int lane = tid & 31;
    const int warp_m = wid & 3;
    const int warp_n = wid >> 2;

    const int m0 = blockIdx.x * 128;
    const int n0 = blockIdx.y * 128;
    const int k0 = blockIdx.z * KSLICE;

    const int lrow = tid >> 3;
    const int lcol = (tid & 7) * 4;

    float acc[2][8][4];
    #pragma unroll
    for (int i = 0; i < 2; i++)
        #pragma unroll
        for (int j = 0; j < 8; j++)
            #pragma unroll
            for (int q = 0; q < 4; q++) acc[i][j][q] = 0.0f;

    const float* __restrict__ Bbase = conv_w + (size_t)n0 * K_GEMM + k0;

    // A-gather row decode (per-thread constants across stages)
    int a_n[16], a_py[16], a_px[16];
    #pragma unroll
    for (int i = 0; i < 16; i++) {
        const int idx = tid + i * 256;
        const int row = idx >> 5;
        const int m = m0 + row;
        const int n = m / 9;
        const int p = m - n * 9;
        a_n[i] = n;
        a_py[i] = p / 3;
        a_px[i] = p - (p / 3) * 3;
    }

    float ra[16];
    float4 rb[4];

    // ---- prefetch + store stage 0 ----
    #pragma unroll
    for (int i = 0; i < 16; i++) {
        const int idx = tid + i * 256;
        const int col = idx & 31;
        const int k = k0 + col;
        const int c = k / 9;
        const int kk = k - c * 9;
        const int ky = kk / 3;
        const int kx = kk - ky * 3;
        const int iy = a_py[i] + ky - 1;
        const int ix = a_px[i] + kx - 1;
        ra[i] = ((unsigned)iy < 3u && (unsigned)ix < 3u)
              ? g_R[((size_t)a_n[i] * CCH + c) * 9 + iy * 3 + ix] : 0.0f;
    }
    #pragma unroll
    for (int q = 0; q < 4; q++)
        rb[q] = *(const float4*)(Bbase + (size_t)(lrow + q * 32) * K_GEMM + lcol);

    {
        float* sAh = smx;
        float* sAl = sAh + TILE_F;
        float* sBh = sAl + TILE_F;
        float* sBl = sBh + TILE_F;
        #pragma unroll
        for (int i = 0; i < 16; i++) {
            const int idx = tid + i * 256;
            const int row = idx >> 5;
            const int col = idx & 31;
            const float h = f2tf32(ra[i]);
            sAh[row * SROW + col] = h;
            sAl[row * SROW + col] = f2tf32(ra[i] - h);
        }
        #pragma unroll
        for (int q = 0; q < 4; q++) {
            const int row = lrow + q * 32;
            float4 h, l;
            h.x = f2tf32(rb[q].x); h.y = f2tf32(rb[q].y);
            h.z = f2tf32(rb[q].z); h.w = f2tf32(rb[q].w);
            l.x = f2tf32(rb[q].x - h.x); l.y = f2tf32(rb[q].y - h.y);
            l.z = f2tf32(rb[q].z - h.z); l.w = f2tf32(rb[q].w - h.w);
            *(float4*)(&sBh[row * SROW + lcol]) = h;
            *(float4*)(&sBl[row * SROW + lcol]) = l;
        }
    }
    __syncthreads();

    for (int s = 0; s < NSTAGE; s++) {
        // issue next-stage loads (latency hidden under compute below)
        if (s + 1 < NSTAGE) {
            const int kbase = k0 + (s + 1) * BK;
            #pragma unroll
            for (int i = 0; i < 16; i++) {
                const int idx = tid + i * 256;
                const int col = idx & 31;
                const int k = kbase + col;
                const int c = k / 9;
                const int kk = k - c * 9;
                const int ky = kk / 3;
                const int kx = kk - ky * 3;
                const int iy = a_py[i] + ky - 1;
                const int ix = a_px[i] + kx - 1;
                ra[i] = ((unsigned)iy < 3u && (unsigned)ix < 3u)
                      ? g_R[((size_t)a_n[i] * CCH + c) * 9 + iy * 3 + ix] : 0.0f;
            }
            #pragma unroll
            for (int q = 0; q < 4; q++)
                rb[q] = *(const float4*)(Bbase + (size_t)(lrow + q * 32) * K_GEMM
                                         + (s + 1) * BK + lcol);
        }

        // compute from buffer s&1
        {
            const float* sAh = smx + (s & 1) * (4 * TILE_F);
            const float* sAl = sAh + TILE_F;
            const float* sBh = sAl + TILE_F;
            const float* sBl = sBh + TILE_F;

            const int rbase = warp_m * 32 + (lane >> 2);
            const int nbase = warp_n * 64 + (lane >> 2);
            #pragma unroll
            for (int kc = 0; kc < 4; kc++) {
                const int kb = kc * 8 + (lane & 3);
                uint32_t ah[2][4], al[2][4];
                #pragma unroll
                for (int i = 0; i < 2; i++) {
                    const int r = rbase + i * 16;
                    ah[i][0] = __float_as_uint(sAh[r * SROW + kb]);
                    ah[i][1] = __float_as_uint(sAh[(r + 8) * SROW + kb]);
                    ah[i][2] = __float_as_uint(sAh[r * SROW + kb + 4]);
                    ah[i][3] = __float_as_uint(sAh[(r + 8) * SROW + kb + 4]);
                    al[i][0] = __float_as_uint(sAl[r * SROW + kb]);
                    al[i][1] = __float_as_uint(sAl[(r + 8) * SROW + kb]);
                    al[i][2] = __float_as_uint(sAl[r * SROW + kb + 4]);
                    al[i][3] = __float_as_uint(sAl[(r + 8) * SROW + kb + 4]);
                }
                #pragma unroll
                for (int j = 0; j < 8; j++) {
                    const int nn = nbase + j * 8;
                    const uint32_t bh0 = __float_as_uint(sBh[nn * SROW + kb]);
                    const uint32_t bh1 = __float_as_uint(sBh[nn * SROW + kb + 4]);
                    const uint32_t bl0 = __float_as_uint(sBl[nn * SROW + kb]);
                    const uint32_t bl1 = __float_as_uint(sBl[nn * SROW + kb + 4]);
                    #pragma unroll
                    for (int i = 0; i < 2; i++) {
                        mma_tf32(acc[i][j], ah[i][0], ah[i][1], ah[i][2], ah[i][3], bh0, bh1);
                        mma_tf32(acc[i][j], ah[i][0], ah[i][1], ah[i][2], ah[i][3], bl0, bl1);
                        mma_tf32(acc[i][j], al[i][0], al[i][1], al[i][2], al[i][3], bh0, bh1);
                    }
                }
            }
        }

        // store next stage into the other buffer (free: last read 2 stages ago)
        if (s + 1 < NSTAGE) {
            float* dAh = smx + ((s + 1) & 1) * (4 * TILE_F);
            float* dAl = dAh + TILE_F;
            float* dBh = dAl + TILE_F;
            float* dBl = dBh + TILE_F;
            #pragma unroll
            for (int i = 0; i < 16; i++) {
                const int idx = tid + i * 256;
                const int row = idx >> 5;
                const int col = idx & 31;
                const float h = f2tf32(ra[i]);
                dAh[row * SROW + col] = h;
                dAl[row * SROW + col] = f2tf32(ra[i] - h);
            }
            #pragma unroll
            for (int q = 0; q < 4; q++) {
                const int row = lrow + q * 32;
                float4 h, l;
                h.x = f2tf32(rb[q].x); h.y = f2tf32(rb[q].y);
                h.z = f2tf32(rb[q].z); h.w = f2tf32(rb[q].w);
                l.x = f2tf32(rb[q].x - h.x); l.y = f2tf32(rb[q].y - h.y);
                l.z = f2tf32(rb[q].z - h.z); l.w = f2tf32(rb[q].w - h.w);
                *(float4*)(&dBh[row * SROW + lcol]) = h;
                *(float4*)(&dBl[row * SROW + lcol]) = l;
            }
        }
        __syncthreads();
    }

    float* __restrict__ hp = g_hpart + (size_t)blockIdx.z * ((size_t)M_GEMM * N_GEMM);
    #pragma unroll
    for (int i = 0; i < 2; i++) {
        const int row = m0 + warp_m * 32 + i * 16 + (lane >> 2);
        #pragma unroll
        for (int j = 0; j < 8; j++) {
            const int col = n0 + warp_n * 64 + j * 8 + 2 * (lane & 3);
            *(float2*)(hp + (size_t)row * N_GEMM + col) =
                make_float2(acc[i][j][0], acc[i][j][1]);
            *(float2*)(hp + (size_t)(row + 8) * N_GEMM + col) =
                make_float2(acc[i][j][2], acc[i][j][3]);
        }
    }
}

// ---------------------------------------------------------------------------
// K3a: streaming split-K reduce: g_h = sum_sp g_hpart[sp].
// ---------------------------------------------------------------------------
__global__ void __launch_bounds__(256) k_reduce()
{
    const size_t i4 = (size_t)blockIdx.x * 256 + threadIdx.x;
    const float4* __restrict__ hp = (const float4*)g_hpart;
    const size_t stride4 = (size_t)M_GEMM * N_GEMM / 4;

    float4 s = hp[i4];
    #pragma unroll
    for (int sp = 1; sp < SPLITK; sp++) {
        const float4 v = hp[(size_t)sp * stride4 + i4];
        s.x += v.x; s.y += v.y; s.z += v.z; s.w += v.w;
    }
    ((float4*)g_h)[i4] = s;
}

// ---------------------------------------------------------------------------
// K3b: per-roi epilogue, 1024 threads, float4 weight loads.
// ---------------------------------------------------------------------------
__global__ void __launch_bounds__(1024) k_epilogue(
    const float* __restrict__ boxes,
    const float* __restrict__ gn_scale, const float* __restrict__ gn_bias,
    const float* __restrict__ head_w,   const float* __restrict__ head_b,
    const float* __restrict__ spat_w,   const float* __restrict__ spat_b,
    const float* __restrict__ sym_emb,
    const float* __restrict__ fuse_w,   const float* __restrict__ fuse_b,
    const int*   __restrict__ sym_ids,
    float* __restrict__ out)
{
    const int n   = blockIdx.x;
    const int tid = threadIdx.x;
    const int w   = tid >> 5;     // 0..31
    const int l   = tid & 31;

    __shared__ __align__(16) float sbuf[256];
    __shared__ __align__(16) float fbuf[256];
    __shared__ float hobuf[256];

    const int sym = sym_ids[n];

    // ---- Phase 1: GN + relu + spatial mean (threads 0..255; warp == group) ----
    if (tid < 256) {
        const int e = tid;
        float hvp[9];
        #pragma unroll
        for (int p = 0; p < 9; p++)
            hvp[p] = g_h[(size_t)(n*9 + p) * N_GEMM + e];

        float lsum = 0.0f;
        #pragma unroll
        for (int p = 0; p < 9; p++) lsum += hvp[p];
        #pragma unroll
        for (int o = 16; o > 0; o >>= 1) lsum += __shfl_xor_sync(0xffffffffu, lsum, o);
        const float mean = lsum * (1.0f / 288.0f);

        float lsq = 0.0f;
        #pragma unroll
        for (int p = 0; p < 9; p++) { float d = hvp[p] - mean; lsq += d * d; }
        #pragma unroll
        for (int o = 16; o > 0; o >>= 1) lsq += __shfl_xor_sync(0xffffffffu, lsq, o);
        const float inv = rsqrtf(lsq * (1.0f / 288.0f) + 1e-5f);

        const float sc = gn_scale[e];
        const float bi = gn_bias[e];
        float acc = 0.0f;
        #pragma unroll
        for (int p = 0; p < 9; p++)
            acc += fmaxf((hvp[p] - mean) * inv * sc + bi, 0.0f);
        sbuf[e] = acc * (1.0f / 9.0f);
    }
    __syncthreads();

    // ---- Phase 2: head GEMV, float4 loads (warp w -> outputs w*8..w*8+7) ----
    {
        const float4 sva = *(const float4*)&sbuf[l * 4];
        const float4 svb = *(const float4*)&sbuf[128 + l * 4];

        float a[8];
        #pragma unroll
        for (int o = 0; o < 8; o++) {
            const float* __restrict__ row = head_w + (size_t)(w * 8 + o) * 256;
            const float4 wa = *(const float4*)(row + l * 4);
            const float4 wb = *(const float4*)(row + 128 + l * 4);
            float t = sva.x * wa.x + sva.y * wa.y + sva.z * wa.z + sva.w * wa.w;
            t = fmaf(svb.x, wb.x, t); t = fmaf(svb.y, wb.y, t);
            t = fmaf(svb.z, wb.z, t); t = fmaf(svb.w, wb.w, t);
            a[o] = t;
        }
        #pragma unroll
        for (int o = 0; o < 8; o++) {
            #pragma unroll
            for (int off = 16; off > 0; off >>= 1)
                a[o] += __shfl_xor_sync(0xffffffffu, a[o], off);
        }
        if (l < 8) {
            const int e = w * 8 + l;
            float v = a[0];
            #pragma unroll
            for (int o = 1; o < 8; o++) v = (l == o) ? a[o] : v;
            hobuf[e] = v + head_b[e];
        }
    }
    __syncthreads();

    // ---- fused vector (threads 0..255) ----
    if (tid < 256) {
        const int e = tid;
        const float ho = fmaxf(hobuf[e], 0.0f);
        const float b0 = boxes[n*4+0], b1 = boxes[n*4+1],
                    b2 = boxes[n*4+2], b3 = boxes[n*4+3];
        float sp = spat_b[e] + b0 * spat_w[e*4+0] + b1 * spat_w[e*4+1]
                             + b2 * spat_w[e*4+2] + b3 * spat_w[e*4+3];
        sp = fmaxf(sp, 0.0f);
        fbuf[e] = ho + sp + sym_emb[sym * 256 + e];
    }
    __syncthreads();

    // ---- Phase 3: fuse GEMV, float4 loads ----
    {
        const float4 fva = *(const float4*)&fbuf[l * 4];
        const float4 fvb = *(const float4*)&fbuf[128 + l * 4];

        float a[8];
        #pragma unroll
        for (int o = 0; o < 8; o++) {
            const float* __restrict__ row =
                fuse_w + ((size_t)sym * 256 + (size_t)(w * 8 + o)) * 256;
            const float4 wa = *(const float4*)(row + l * 4);
            const float4 wb = *(const float4*)(row + 128 + l * 4);
            float t = fva.x * wa.x + fva.y * wa.y + fva.z * wa.z + fva.w * wa.w;
            t = fmaf(fvb.x, wb.x, t); t = fmaf(fvb.y, wb.y, t);
            t = fmaf(fvb.z, wb.z, t); t = fmaf(fvb.w, wb.w, t);
            a[o] = t;
        }
        #pragma unroll
        for (int o = 0; o < 8; o++) {
            #pragma unroll
            for (int off = 16; off > 0; off >>= 1)
                a[o] += __shfl_xor_sync(0xffffffffu, a[o], off);
        }
        if (l < 8) {
            const int e = w * 8 + l;
            float v = a[0];
            #pragma unroll
            for (int o = 1; o < 8; o++) v = (l == o) ? a[o] : v;
            out[(size_t)n * 256 + e] = fmaxf(v + fuse_b[sym * 256 + e], 0.0f);
        }
    }
}

// ---------------------------------------------------------------------------
extern "C" void kernel_launch(void* const* d_in, const int* in_sizes, int n_in,
                              void* d_out, int out_size)
{
    const float* fm        = (const float*)d_in[0];
    const float* boxes     = (const float*)d_in[1];
    const float* conv_w    = (const float*)d_in[2];
    const float* gn_scale  = (const float*)d_in[3];
    const float* gn_bias   = (const float*)d_in[4];
    const float* head_w    = (const float*)d_in[5];
    const float* head_b    = (const float*)d_in[6];
    const float* spat_w    = (const float*)d_in[7];
    const float* spat_b    = (const float*)d_in[8];
    const float* sym_emb   = (const float*)d_in[9];
    const float* fuse_w    = (const float*)d_in[10];
    const float* fuse_b    = (const float*)d_in[11];
    const int*   batch_idx = (const int*)d_in[12];
    const int*   level_idx = (const int*)d_in[13];
    const int*   sym_ids   = (const int*)d_in[14];
    float* out = (float*)d_out;

    cudaFuncSetAttribute(k_gemm_mma,
                         cudaFuncAttributeMaxDynamicSharedMemorySize, GEMM_SMEM_BYTES);

    dim3 g1(NROI, 4);
    k_roi<<<g1, 64>>>(fm, boxes, batch_idx, level_idx);

    dim3 g2(M_GEMM / 128, N_GEMM / 128, SPLITK);   // (9, 2, 8) = 144 CTAs
    k_gemm_mma<<<g2, 256, GEMM_SMEM_BYTES>>>(conv_w);

    k_reduce<<<(M_GEMM * N_GEMM / 4) / 256, 256>>>();

    k_epilogue<<<NROI, 1024>>>(boxes, gn_scale, gn_bias, head_w, head_b,
                               spat_w, spat_b, sym_emb, fuse_w, fuse_b,
                               sym_ids, out);
}

// round 7
// speedup vs baseline: 1.6638x; 1.2655x over previous
#include <cuda_runtime.h>
#include <cuda_bf16.h>
#include <math.h>
#include <cstdint>

// ---------------- problem constants ----------------
#define NROI 128
#define CCH  256
#define ECH  256
#define M_GEMM (NROI*9)      // 1152
#define K_GEMM (CCH*9)       // 2304
#define N_GEMM ECH           // 256

#define SPLITK 8
#define KSLICE (K_GEMM/SPLITK)   // 288
#define BK     32
#define NSTAGE (KSLICE/BK)       // 9

// packed-bf16 smem layout: row = 16 uint32 (32 bf16), stride 20 (bank-safe)
#define PSTRIDE 20
#define PTILE   (128*PSTRIDE)                 // uint32 per tile
#define GEMM_SMEM_BYTES (2 * 4 * PTILE * 4)   // 81920 bytes

// ---------------- device scratch (no runtime alloc allowed) ----------------
__device__ __align__(256) float g_R[(size_t)NROI * CCH * 9];               // 1.18 MB
__device__ __align__(256) float g_hpart[(size_t)SPLITK * M_GEMM * N_GEMM]; // 9.4 MB

__device__ __forceinline__ uint32_t bf2pack(float v0, float v1) {
    __nv_bfloat162 t;
    t.x = __float2bfloat16(v0);
    t.y = __float2bfloat16(v1);
    return *reinterpret_cast<uint32_t*>(&t);
}
__device__ __forceinline__ float bfhi(float v) {
    return __bfloat162float(__float2bfloat16(v));
}

__device__ __forceinline__ void mma_bf16(float c[4],
                                         uint32_t a0, uint32_t a1, uint32_t a2, uint32_t a3,
                                         uint32_t b0, uint32_t b1) {
    asm volatile(
        "mma.sync.aligned.m16n8k16.row.col.f32.bf16.bf16.f32 "
        "{%0,%1,%2,%3}, {%4,%5,%6,%7}, {%8,%9}, {%0,%1,%2,%3};"
        : "+f"(c[0]), "+f"(c[1]), "+f"(c[2]), "+f"(c[3])
        : "r"(a0), "r"(a1), "r"(a2), "r"(a3), "r"(b0), "r"(b1));
}

// ---------------------------------------------------------------------------
// K1: ROI-align -> compact R[n][c][9].  grid (NROI, 4) x 64 threads.
// ---------------------------------------------------------------------------
__global__ void __launch_bounds__(64) k_roi(
    const float* __restrict__ fm, const float* __restrict__ boxes,
    const int* __restrict__ batch_idx, const int* __restrict__ level_idx)
{
    const int n = blockIdx.x;
    const int c = blockIdx.y * 64 + threadIdx.x;

    const int lvl = level_idx[n];
    const int b   = batch_idx[n];
    const float stride = (float)(8 << lvl);
    const float hv     = (float)(128 >> lvl);
    const float scale  = 1.0f / stride;

    const float x1 = boxes[n*4+0] * scale;
    const float y1 = boxes[n*4+1] * scale;
    const float x2 = boxes[n*4+2] * scale;
    const float y2 = boxes[n*4+3] * scale;
    const float roi_w = fmaxf(x2 - x1, 1.0f);
    const float roi_h = fmaxf(y2 - y1, 1.0f);

    const float* __restrict__ plane =
        fm + ((size_t)(lvl*2 + b) * CCH + c) * 128 * 128;
    const int hi = (int)(hv - 1.0f);

    float* __restrict__ r = g_R + ((size_t)n * CCH + c) * 9;

    #pragma unroll
    for (int py = 0; py < 3; py++) {
        const float offy = ((float)py + 0.5f) / 3.0f;
        const float y = y1 + offy * roi_h;
        #pragma unroll
        for (int px = 0; px < 3; px++) {
            const float offx = ((float)px + 0.5f) / 3.0f;
            const float x = x1 + offx * roi_w;
            const bool valid = (y > -1.0f) && (y < hv) && (x > -1.0f) && (x < hv);
            const float yc = fminf(fmaxf(y, 0.0f), hv - 1.0f);
            const float xc = fminf(fmaxf(x, 0.0f), hv - 1.0f);
            const int y0 = (int)floorf(yc);
            const int x0 = (int)floorf(xc);
            const int y1i = min(y0 + 1, hi);
            const int x1i = min(x0 + 1, hi);
            const float ly = yc - (float)y0;
            const float lx = xc - (float)x0;
            const float v00 = plane[y0 * 128 + x0];
            const float v01 = plane[y0 * 128 + x1i];
            const float v10 = plane[y1i * 128 + x0];
            const float v11 = plane[y1i * 128 + x1i];
            float val = (1.0f-ly)*(1.0f-lx)*v00 + (1.0f-ly)*lx*v01
                      + ly*(1.0f-lx)*v10 + ly*lx*v11;
            r[py*3 + px] = valid ? val : 0.0f;
        }
    }
}

// ---------------------------------------------------------------------------
// K2: 3x-BF16 mma.sync GEMM (m16n8k16), fused im2col A-gather, double-buffered.
// grid (9, 2, 8) = 144 CTAs, 256 thr (8 warps 4x2), warp tile 32x64.
// ---------------------------------------------------------------------------
__global__ void __launch_bounds__(256, 1) k_gemm_mma(const float* __restrict__ conv_w)
{
    extern __shared__ uint32_t smu[];   // [2 buf][Ah|Al|Bh|Bl][128*PSTRIDE]

    const int tid  = threadIdx.x;
    const int wid  = tid >> 5;
    const int lane = tid & 31;
    const int warp_m = wid & 3;
    const int warp_n = wid >> 2;

    const int m0 = blockIdx.x * 128;
    const int n0 = blockIdx.y * 128;
    const int k0 = blockIdx.z * KSLICE;

    const int pc   = tid & 15;          // A packed col (constant per thread)
    const int lrow = tid >> 3;          // B gmem row base
    const int lcol = (tid & 7) * 4;     // B gmem k offset (float4)

    float acc[2][8][4];
    #pragma unroll
    for (int i = 0; i < 2; i++)
        #pragma unroll
        for (int j = 0; j < 8; j++)
            #pragma unroll
            for (int q = 0; q < 4; q++) acc[i][j][q] = 0.0f;

    const float* __restrict__ Bbase = conv_w + (size_t)n0 * K_GEMM + k0;

    // A-gather row decode: rows (tid>>4) + i*16, i<8
    int a_n[8], a_py[8], a_px[8];
    #pragma unroll
    for (int i = 0; i < 8; i++) {
        const int row = (tid >> 4) + i * 16;
        const int m = m0 + row;
        const int n = m / 9;
        const int p = m - n * 9;
        a_n[i] = n;
        a_py[i] = p / 3;
        a_px[i] = p - (p / 3) * 3;
    }

    float ra[16];
    float4 rb[4];

    // ---- gather helper (stage kbase) inlined twice ----
    #define GATHER_A(kbase_)                                                   \
        _Pragma("unroll")                                                      \
        for (int i = 0; i < 8; i++) {                                          \
            _Pragma("unroll")                                                  \
            for (int t = 0; t < 2; t++) {                                      \
                const int k = (kbase_) + pc * 2 + t;                           \
                const int c = k / 9;                                           \
                const int kk = k - c * 9;                                      \
                const int ky = kk / 3, kx = kk - ky * 3;                       \
                const int iy = a_py[i] + ky - 1, ix = a_px[i] + kx - 1;        \
                ra[2*i+t] = ((unsigned)iy < 3u && (unsigned)ix < 3u)           \
                    ? g_R[((size_t)a_n[i] * CCH + c) * 9 + iy * 3 + ix] : 0.0f;\
            }                                                                  \
        }

    #define STORE_STAGE(bufsel)                                                \
        {                                                                      \
            uint32_t* dAh = smu + (bufsel) * (4 * PTILE);                      \
            uint32_t* dAl = dAh + PTILE;                                       \
            uint32_t* dBh = dAl + PTILE;                                       \
            uint32_t* dBl = dBh + PTILE;                                       \
            _Pragma("unroll")                                                  \
            for (int i = 0; i < 8; i++) {                                      \
                const int row = (tid >> 4) + i * 16;                           \
                const float v0 = ra[2*i], v1 = ra[2*i+1];                      \
                dAh[row * PSTRIDE + pc] = bf2pack(v0, v1);                     \
                dAl[row * PSTRIDE + pc] = bf2pack(v0 - bfhi(v0), v1 - bfhi(v1));\
            }                                                                  \
            _Pragma("unroll")                                                  \
            for (int q = 0; q < 4; q++) {                                      \
                const int row = (tid >> 3) + q * 32;                           \
                const float4 v = rb[q];                                        \
                const int base = row * PSTRIDE + (tid & 7) * 2;                \
                dBh[base]     = bf2pack(v.x, v.y);                             \
                dBh[base + 1] = bf2pack(v.z, v.w);                             \
                dBl[base]     = bf2pack(v.x - bfhi(v.x), v.y - bfhi(v.y));     \
                dBl[base + 1] = bf2pack(v.z - bfhi(v.z), v.w - bfhi(v.w));     \
            }                                                                  \
        }

    // stage 0 prefetch + store
    GATHER_A(k0)
    #pragma unroll
    for (int q = 0; q < 4; q++)
        rb[q] = *(const float4*)(Bbase + (size_t)(lrow + q * 32) * K_GEMM + lcol);
    STORE_STAGE(0)
    __syncthreads();

    for (int s = 0; s < NSTAGE; s++) {
        // issue next-stage gmem loads
        if (s + 1 < NSTAGE) {
            GATHER_A(k0 + (s + 1) * BK)
            #pragma unroll
            for (int q = 0; q < 4; q++)
                rb[q] = *(const float4*)(Bbase + (size_t)(lrow + q * 32) * K_GEMM
                                         + (s + 1) * BK + lcol);
        }

        // compute from buffer s&1
        {
            const uint32_t* sAh = smu + (s & 1) * (4 * PTILE);
            const uint32_t* sAl = sAh + PTILE;
            const uint32_t* sBh = sAl + PTILE;
            const uint32_t* sBl = sBh + PTILE;

            const int rbase = warp_m * 32 + (lane >> 2);
            const int nbase = warp_n * 64 + (lane >> 2);
            #pragma unroll
            for (int kc = 0; kc < 2; kc++) {
                const int kb = kc * 8 + (lane & 3);
                uint32_t ah[2][4], al[2][4];
                #pragma unroll
                for (int i = 0; i < 2; i++) {
                    const int r = rbase + i * 16;
                    ah[i][0] = sAh[r * PSTRIDE + kb];
                    ah[i][1] = sAh[(r + 8) * PSTRIDE + kb];
                    ah[i][2] = sAh[r * PSTRIDE + kb + 4];
                    ah[i][3] = sAh[(r + 8) * PSTRIDE + kb + 4];
                    al[i][0] = sAl[r * PSTRIDE + kb];
                    al[i][1] = sAl[(r + 8) * PSTRIDE + kb];
                    al[i][2] = sAl[r * PSTRIDE + kb + 4];
                    al[i][3] = sAl[(r + 8) * PSTRIDE + kb + 4];
                }
                #pragma unroll
                for (int j = 0; j < 8; j++) {
                    const int nn = nbase + j * 8;
                    const uint32_t bh0 = sBh[nn * PSTRIDE + kb];
                    const uint32_t bh1 = sBh[nn * PSTRIDE + kb + 4];
                    const uint32_t bl0 = sBl[nn * PSTRIDE + kb];
                    const uint32_t bl1 = sBl[nn * PSTRIDE + kb + 4];
                    #pragma unroll
                    for (int i = 0; i < 2; i++) {
                        mma_bf16(acc[i][j], ah[i][0], ah[i][1], ah[i][2], ah[i][3], bh0, bh1);
                        mma_bf16(acc[i][j], ah[i][0], ah[i][1], ah[i][2], ah[i][3], bl0, bl1);
                        mma_bf16(acc[i][j], al[i][0], al[i][1], al[i][2], al[i][3], bh0, bh1);
                    }
                }
            }
        }

        // store next stage into other buffer
        if (s + 1 < NSTAGE) {
            STORE_STAGE((s + 1) & 1)
        }
        __syncthreads();
    }

    float* __restrict__ hp = g_hpart + (size_t)blockIdx.z * ((size_t)M_GEMM * N_GEMM);
    #pragma unroll
    for (int i = 0; i < 2; i++) {
        const int row = m0 + warp_m * 32 + i * 16 + (lane >> 2);
        #pragma unroll
        for (int j = 0; j < 8; j++) {
            const int col = n0 + warp_n * 64 + j * 8 + 2 * (lane & 3);
            *(float2*)(hp + (size_t)row * N_GEMM + col) =
                make_float2(acc[i][j][0], acc[i][j][1]);
            *(float2*)(hp + (size_t)(row + 8) * N_GEMM + col) =
                make_float2(acc[i][j][2], acc[i][j][3]);
        }
    }
}

// ---------------------------------------------------------------------------
// K3: per-roi epilogue with fused split-K reduce. 1024 threads.
// ---------------------------------------------------------------------------
__global__ void __launch_bounds__(1024) k_epilogue(
    const float* __restrict__ boxes,
    const float* __restrict__ gn_scale, const float* __restrict__ gn_bias,
    const float* __restrict__ head_w,   const float* __restrict__ head_b,
    const float* __restrict__ spat_w,   const float* __restrict__ spat_b,
    const float* __restrict__ sym_emb,
    const float* __restrict__ fuse_w,   const float* __restrict__ fuse_b,
    const int*   __restrict__ sym_ids,
    float* __restrict__ out)
{
    const int n   = blockIdx.x;
    const int tid = threadIdx.x;
    const int w   = tid >> 5;
    const int l   = tid & 31;

    __shared__ __align__(16) float hred[9 * 256];
    __shared__ __align__(16) float sbuf[256];
    __shared__ __align__(16) float fbuf[256];
    __shared__ float hobuf[256];

    const int sym = sym_ids[n];
    const size_t sk_stride = (size_t)M_GEMM * N_GEMM;

    // ---- Phase 0: split-K reduce for this roi's 9x256 block ----
    #pragma unroll
    for (int v = tid; v < 9 * 256; v += 1024) {
        const size_t off = (size_t)(n * 9) * N_GEMM + v;
        float s = 0.0f;
        #pragma unroll
        for (int sp = 0; sp < SPLITK; sp++)
            s += g_hpart[(size_t)sp * sk_stride + off];
        hred[v] = s;
    }
    __syncthreads();

    // ---- Phase 1: GN + relu + spatial mean (threads 0..255; warp == group) ----
    if (tid < 256) {
        const int e = tid;
        float hvp[9];
        #pragma unroll
        for (int p = 0; p < 9; p++)
            hvp[p] = hred[p * 256 + e];

        float lsum = 0.0f;
        #pragma unroll
        for (int p = 0; p < 9; p++) lsum += hvp[p];
        #pragma unroll
        for (int o = 16; o > 0; o >>= 1) lsum += __shfl_xor_sync(0xffffffffu, lsum, o);
        const float mean = lsum * (1.0f / 288.0f);

        float lsq = 0.0f;
        #pragma unroll
        for (int p = 0; p < 9; p++) { float d = hvp[p] - mean; lsq += d * d; }
        #pragma unroll
        for (int o = 16; o > 0; o >>= 1) lsq += __shfl_xor_sync(0xffffffffu, lsq, o);
        const float inv = rsqrtf(lsq * (1.0f / 288.0f) + 1e-5f);

        const float sc = gn_scale[e];
        const float bi = gn_bias[e];
        float acc = 0.0f;
        #pragma unroll
        for (int p = 0; p < 9; p++)
            acc += fmaxf((hvp[p] - mean) * inv * sc + bi, 0.0f);
        sbuf[e] = acc * (1.0f / 9.0f);
    }
    __syncthreads();

    // ---- Phase 2: head GEMV (warp w -> outputs w*8..w*8+7, float4 loads) ----
    {
        const float4 sva = *(const float4*)&sbuf[l * 4];
        const float4 svb = *(const float4*)&sbuf[128 + l * 4];

        float a[8];
        #pragma unroll
        for (int o = 0; o < 8; o++) {
            const float* __restrict__ row = head_w + (size_t)(w * 8 + o) * 256;
            const float4 wa = *(const float4*)(row + l * 4);
            const float4 wb = *(const float4*)(row + 128 + l * 4);
            float t = sva.x * wa.x + sva.y * wa.y + sva.z * wa.z + sva.w * wa.w;
            t = fmaf(svb.x, wb.x, t); t = fmaf(svb.y, wb.y, t);
            t = fmaf(svb.z, wb.z, t); t = fmaf(svb.w, wb.w, t);
            a[o] = t;
        }
        #pragma unroll
        for (int o = 0; o < 8; o++) {
            #pragma unroll
            for (int off = 16; off > 0; off >>= 1)
                a[o] += __shfl_xor_sync(0xffffffffu, a[o], off);
        }
        if (l < 8) {
            const int e = w * 8 + l;
            float v = a[0];
            #pragma unroll
            for (int o = 1; o < 8; o++) v = (l == o) ? a[o] : v;
            hobuf[e] = v + head_b[e];
        }
    }
    __syncthreads();

    // ---- fused vector (threads 0..255) ----
    if (tid < 256) {
        const int e = tid;
        const float ho = fmaxf(hobuf[e], 0.0f);
        const float b0 = boxes[n*4+0], b1 = boxes[n*4+1],
                    b2 = boxes[n*4+2], b3 = boxes[n*4+3];
        float sp = spat_b[e] + b0 * spat_w[e*4+0] + b1 * spat_w[e*4+1]
                             + b2 * spat_w[e*4+2] + b3 * spat_w[e*4+3];
        sp = fmaxf(sp, 0.0f);
        fbuf[e] = ho + sp + sym_emb[sym * 256 + e];
    }
    __syncthreads();

    // ---- Phase 3: fuse GEMV ----
    {
        const float4 fva = *(const float4*)&fbuf[l * 4];
        const float4 fvb = *(const float4*)&fbuf[128 + l * 4];

        float a[8];
        #pragma unroll
        for (int o = 0; o < 8; o++) {
            const float* __restrict__ row =
                fuse_w + ((size_t)sym * 256 + (size_t)(w * 8 + o)) * 256;
            const float4 wa = *(const float4*)(row + l * 4);
            const float4 wb = *(const float4*)(row + 128 + l * 4);
            float t = fva.x * wa.x + fva.y * wa.y + fva.z * wa.z + fva.w * wa.w;
            t = fmaf(fvb.x, wb.x, t); t = fmaf(fvb.y, wb.y, t);
            t = fmaf(fvb.z, wb.z, t); t = fmaf(fvb.w, wb.w, t);
            a[o] = t;
        }
        #pragma unroll
        for (int o = 0; o < 8; o++) {
            #pragma unroll
            for (int off = 16; off > 0; off >>= 1)
                a[o] += __shfl_xor_sync(0xffffffffu, a[o], off);
        }
        if (l < 8) {
            const int e = w * 8 + l;
            float v = a[0];
            #pragma unroll
            for (int o = 1; o < 8; o++) v = (l == o) ? a[o] : v;
            out[(size_t)n * 256 + e] = fmaxf(v + fuse_b[sym * 256 + e], 0.0f);
        }
    }
}

// ---------------------------------------------------------------------------
extern "C" void kernel_launch(void* const* d_in, const int* in_sizes, int n_in,
                              void* d_out, int out_size)
{
    const float* fm        = (const float*)d_in[0];
    const float* boxes     = (const float*)d_in[1];
    const float* conv_w    = (const float*)d_in[2];
    const float* gn_scale  = (const float*)d_in[3];
    const float* gn_bias   = (const float*)d_in[4];
    const float* head_w    = (const float*)d_in[5];
    const float* head_b    = (const float*)d_in[6];
    const float* spat_w    = (const float*)d_in[7];
    const float* spat_b    = (const float*)d_in[8];
    const float* sym_emb   = (const float*)d_in[9];
    const float* fuse_w    = (const float*)d_in[10];
    const float* fuse_b    = (const float*)d_in[11];
    const int*   batch_idx = (const int*)d_in[12];
    const int*   level_idx = (const int*)d_in[13];
    const int*   sym_ids   = (const int*)d_in[14];
    float* out = (float*)d_out;

    cudaFuncSetAttribute(k_gemm_mma,
                         cudaFuncAttributeMaxDynamicSharedMemorySize, GEMM_SMEM_BYTES);

    dim3 g1(NROI, 4);
    k_roi<<<g1, 64>>>(fm, boxes, batch_idx, level_idx);

    dim3 g2(M_GEMM / 128, N_GEMM / 128, SPLITK);   // (9, 2, 8) = 144 CTAs
    k_gemm_mma<<<g2, 256, GEMM_SMEM_BYTES>>>(conv_w);

    k_epilogue<<<NROI, 1024>>>(boxes, gn_scale, gn_bias, head_w, head_b,
                               spat_w, spat_b, sym_emb, fuse_w, fuse_b,
                               sym_ids, out);
}

// round 8
// speedup vs baseline: 1.6781x; 1.0086x over previous
#include <cuda_runtime.h>
#include <cuda_bf16.h>
#include <math.h>
#include <cstdint>

// ---------------- problem constants ----------------
#define NROI 128
#define CCH  256
#define ECH  256
#define M_GEMM (NROI*9)      // 1152
#define K_GEMM (CCH*9)       // 2304
#define N_GEMM ECH           // 256

#define SPLITK 8
#define KSLICE (K_GEMM/SPLITK)   // 288
#define BK     32
#define NSTAGE (KSLICE/BK)       // 9

// packed-bf16 smem layout: row = 16 uint32 (32 bf16), stride 20 (bank-safe)
#define PSTRIDE 20
#define PTILE   (128*PSTRIDE)                 // uint32 per tile
#define GEMM_SMEM_BYTES (2 * 4 * PTILE * 4)   // 81920 bytes

// ---------------- device scratch (no runtime alloc allowed) ----------------
// g_R layout: [n][p][c]  (point-major so roi writes coalesce)
__device__ __align__(256) float g_R[(size_t)NROI * 9 * CCH];               // 1.18 MB
__device__ __align__(256) float g_hpart[(size_t)SPLITK * M_GEMM * N_GEMM]; // 9.4 MB

__device__ __forceinline__ uint32_t bf2pack(float v0, float v1) {
    __nv_bfloat162 t;
    t.x = __float2bfloat16(v0);
    t.y = __float2bfloat16(v1);
    return *reinterpret_cast<uint32_t*>(&t);
}
__device__ __forceinline__ float bfhi(float v) {
    return __bfloat162float(__float2bfloat16(v));
}

__device__ __forceinline__ void mma_bf16(float c[4],
                                         uint32_t a0, uint32_t a1, uint32_t a2, uint32_t a3,
                                         uint32_t b0, uint32_t b1) {
    asm volatile(
        "mma.sync.aligned.m16n8k16.row.col.f32.bf16.bf16.f32 "
        "{%0,%1,%2,%3}, {%4,%5,%6,%7}, {%8,%9}, {%0,%1,%2,%3};"
        : "+f"(c[0]), "+f"(c[1]), "+f"(c[2]), "+f"(c[3])
        : "r"(a0), "r"(a1), "r"(a2), "r"(a3), "r"(b0), "r"(b1));
}

// ---------------------------------------------------------------------------
// K1: ROI-align -> compact R[n][p][c].  grid (NROI, 9) x 256 threads.
// One CTA per (roi, sample point); thread = channel; 4 taps per thread.
// ---------------------------------------------------------------------------
__global__ void __launch_bounds__(256) k_roi(
    const float* __restrict__ fm, const float* __restrict__ boxes,
    const int* __restrict__ batch_idx, const int* __restrict__ level_idx)
{
    const int n = blockIdx.x;
    const int p = blockIdx.y;           // 0..8
    const int c = threadIdx.x;
    const int py = p / 3, px = p - py * 3;

    const int lvl = level_idx[n];
    const int b   = batch_idx[n];
    const float stride = (float)(8 << lvl);
    const float hv     = (float)(128 >> lvl);
    const float scale  = 1.0f / stride;

    const float x1 = boxes[n*4+0] * scale;
    const float y1 = boxes[n*4+1] * scale;
    const float x2 = boxes[n*4+2] * scale;
    const float y2 = boxes[n*4+3] * scale;
    const float roi_w = fmaxf(x2 - x1, 1.0f);
    const float roi_h = fmaxf(y2 - y1, 1.0f);

    const float y = y1 + (((float)py + 0.5f) / 3.0f) * roi_h;
    const float x = x1 + (((float)px + 0.5f) / 3.0f) * roi_w;
    const bool valid = (y > -1.0f) && (y < hv) && (x > -1.0f) && (x < hv);

    const float yc = fminf(fmaxf(y, 0.0f), hv - 1.0f);
    const float xc = fminf(fmaxf(x, 0.0f), hv - 1.0f);
    const int y0 = (int)floorf(yc);
    const int x0 = (int)floorf(xc);
    const int hi = (int)(hv - 1.0f);
    const int y1i = min(y0 + 1, hi);
    const int x1i = min(x0 + 1, hi);
    const float ly = yc - (float)y0;
    const float lx = xc - (float)x0;

    const float* __restrict__ plane =
        fm + ((size_t)(lvl*2 + b) * CCH + c) * 128 * 128;

    const float v00 = plane[y0 * 128 + x0];
    const float v01 = plane[y0 * 128 + x1i];
    const float v10 = plane[y1i * 128 + x0];
    const float v11 = plane[y1i * 128 + x1i];
    float val = (1.0f-ly)*(1.0f-lx)*v00 + (1.0f-ly)*lx*v01
              + ly*(1.0f-lx)*v10 + ly*lx*v11;

    g_R[(size_t)(n * 9 + p) * CCH + c] = valid ? val : 0.0f;
}

// ---------------------------------------------------------------------------
// K2: 3x-BF16 mma.sync GEMM (m16n8k16), fused im2col A-gather, double-buffered.
// grid (9, 2, 8) = 144 CTAs, 256 thr (8 warps 4x2), warp tile 32x64.
// ---------------------------------------------------------------------------
__global__ void __launch_bounds__(256, 1) k_gemm_mma(const float* __restrict__ conv_w)
{
    extern __shared__ uint32_t smu[];   // [2 buf][Ah|Al|Bh|Bl][128*PSTRIDE]

    const int tid  = threadIdx.x;
    const int wid  = tid >> 5;
    const int lane = tid & 31;
    const int warp_m = wid & 3;
    const int warp_n = wid >> 2;

    const int m0 = blockIdx.x * 128;
    const int n0 = blockIdx.y * 128;
    const int k0 = blockIdx.z * KSLICE;

    const int pc   = tid & 15;          // A packed col (constant per thread)
    const int lrow = tid >> 3;          // B gmem row base
    const int lcol = (tid & 7) * 4;     // B gmem k offset (float4)

    float acc[2][8][4];
    #pragma unroll
    for (int i = 0; i < 2; i++)
        #pragma unroll
        for (int j = 0; j < 8; j++)
            #pragma unroll
            for (int q = 0; q < 4; q++) acc[i][j][q] = 0.0f;

    const float* __restrict__ Bbase = conv_w + (size_t)n0 * K_GEMM + k0;

    // A-gather row decode: rows (tid>>4) + i*16, i<8
    int a_n[8], a_py[8], a_px[8];
    #pragma unroll
    for (int i = 0; i < 8; i++) {
        const int row = (tid >> 4) + i * 16;
        const int m = m0 + row;
        const int n = m / 9;
        const int p = m - n * 9;
        a_n[i] = n;
        a_py[i] = p / 3;
        a_px[i] = p - (p / 3) * 3;
    }

    float ra[16];
    float4 rb[4];

    // ---- gather helper (stage kbase) ----
    #define GATHER_A(kbase_)                                                   \
        _Pragma("unroll")                                                      \
        for (int i = 0; i < 8; i++) {                                          \
            _Pragma("unroll")                                                  \
            for (int t = 0; t < 2; t++) {                                      \
                const int k = (kbase_) + pc * 2 + t;                           \
                const int c = k / 9;                                           \
                const int kk = k - c * 9;                                      \
                const int ky = kk / 3, kx = kk - ky * 3;                       \
                const int iy = a_py[i] + ky - 1, ix = a_px[i] + kx - 1;        \
                ra[2*i+t] = ((unsigned)iy < 3u && (unsigned)ix < 3u)           \
                    ? g_R[(size_t)(a_n[i] * 9 + iy * 3 + ix) * CCH + c] : 0.0f;\
            }                                                                  \
        }

    #define STORE_STAGE(bufsel)                                                \
        {                                                                      \
            uint32_t* dAh = smu + (bufsel) * (4 * PTILE);                      \
            uint32_t* dAl = dAh + PTILE;                                       \
            uint32_t* dBh = dAl + PTILE;                                       \
            uint32_t* dBl = dBh + PTILE;                                       \
            _Pragma("unroll")                                                  \
            for (int i = 0; i < 8; i++) {                                      \
                const int row = (tid >> 4) + i * 16;                           \
                const float v0 = ra[2*i], v1 = ra[2*i+1];                      \
                dAh[row * PSTRIDE + pc] = bf2pack(v0, v1);                     \
                dAl[row * PSTRIDE + pc] = bf2pack(v0 - bfhi(v0), v1 - bfhi(v1));\
            }                                                                  \
            _Pragma("unroll")                                                  \
            for (int q = 0; q < 4; q++) {                                      \
                const int row = (tid >> 3) + q * 32;                           \
                const float4 v = rb[q];                                        \
                const int base = row * PSTRIDE + (tid & 7) * 2;                \
                dBh[base]     = bf2pack(v.x, v.y);                             \
                dBh[base + 1] = bf2pack(v.z, v.w);                             \
                dBl[base]     = bf2pack(v.x - bfhi(v.x), v.y - bfhi(v.y));     \
                dBl[base + 1] = bf2pack(v.z - bfhi(v.z), v.w - bfhi(v.w));     \
            }                                                                  \
        }

    // stage 0 prefetch + store
    GATHER_A(k0)
    #pragma unroll
    for (int q = 0; q < 4; q++)
        rb[q] = *(const float4*)(Bbase + (size_t)(lrow + q * 32) * K_GEMM + lcol);
    STORE_STAGE(0)
    __syncthreads();

    for (int s = 0; s < NSTAGE; s++) {
        // issue next-stage gmem loads
        if (s + 1 < NSTAGE) {
            GATHER_A(k0 + (s + 1) * BK)
            #pragma unroll
            for (int q = 0; q < 4; q++)
                rb[q] = *(const float4*)(Bbase + (size_t)(lrow + q * 32) * K_GEMM
                                         + (s + 1) * BK + lcol);
        }

        // compute from buffer s&1
        {
            const uint32_t* sAh = smu + (s & 1) * (4 * PTILE);
            const uint32_t* sAl = sAh + PTILE;
            const uint32_t* sBh = sAl + PTILE;
            const uint32_t* sBl = sBh + PTILE;

            const int rbase = warp_m * 32 + (lane >> 2);
            const int nbase = warp_n * 64 + (lane >> 2);
            #pragma unroll
            for (int kc = 0; kc < 2; kc++) {
                const int kb = kc * 8 + (lane & 3);
                uint32_t ah[2][4], al[2][4];
                #pragma unroll
                for (int i = 0; i < 2; i++) {
                    const int r = rbase + i * 16;
                    ah[i][0] = sAh[r * PSTRIDE + kb];
                    ah[i][1] = sAh[(r + 8) * PSTRIDE + kb];
                    ah[i][2] = sAh[r * PSTRIDE + kb + 4];
                    ah[i][3] = sAh[(r + 8) * PSTRIDE + kb + 4];
                    al[i][0] = sAl[r * PSTRIDE + kb];
                    al[i][1] = sAl[(r + 8) * PSTRIDE + kb];
                    al[i][2] = sAl[r * PSTRIDE + kb + 4];
                    al[i][3] = sAl[(r + 8) * PSTRIDE + kb + 4];
                }
                #pragma unroll
                for (int j = 0; j < 8; j++) {
                    const int nn = nbase + j * 8;
                    const uint32_t bh0 = sBh[nn * PSTRIDE + kb];
                    const uint32_t bh1 = sBh[nn * PSTRIDE + kb + 4];
                    const uint32_t bl0 = sBl[nn * PSTRIDE + kb];
                    const uint32_t bl1 = sBl[nn * PSTRIDE + kb + 4];
                    #pragma unroll
                    for (int i = 0; i < 2; i++) {
                        mma_bf16(acc[i][j], ah[i][0], ah[i][1], ah[i][2], ah[i][3], bh0, bh1);
                        mma_bf16(acc[i][j], ah[i][0], ah[i][1], ah[i][2], ah[i][3], bl0, bl1);
                        mma_bf16(acc[i][j], al[i][0], al[i][1], al[i][2], al[i][3], bh0, bh1);
                    }
                }
            }
        }

        // store next stage into other buffer
        if (s + 1 < NSTAGE) {
            STORE_STAGE((s + 1) & 1)
        }
        __syncthreads();
    }

    float* __restrict__ hp = g_hpart + (size_t)blockIdx.z * ((size_t)M_GEMM * N_GEMM);
    #pragma unroll
    for (int i = 0; i < 2; i++) {
        const int row = m0 + warp_m * 32 + i * 16 + (lane >> 2);
        #pragma unroll
        for (int j = 0; j < 8; j++) {
            const int col = n0 + warp_n * 64 + j * 8 + 2 * (lane & 3);
            *(float2*)(hp + (size_t)row * N_GEMM + col) =
                make_float2(acc[i][j][0], acc[i][j][1]);
            *(float2*)(hp + (size_t)(row + 8) * N_GEMM + col) =
                make_float2(acc[i][j][2], acc[i][j][3]);
        }
    }
}

// ---------------------------------------------------------------------------
// K3: per-roi epilogue with fused split-K reduce. 1024 threads.
// ---------------------------------------------------------------------------
__global__ void __launch_bounds__(1024) k_epilogue(
    const float* __restrict__ boxes,
    const float* __restrict__ gn_scale, const float* __restrict__ gn_bias,
    const float* __restrict__ head_w,   const float* __restrict__ head_b,
    const float* __restrict__ spat_w,   const float* __restrict__ spat_b,
    const float* __restrict__ sym_emb,
    const float* __restrict__ fuse_w,   const float* __restrict__ fuse_b,
    const int*   __restrict__ sym_ids,
    float* __restrict__ out)
{
    const int n   = blockIdx.x;
    const int tid = threadIdx.x;
    const int w   = tid >> 5;
    const int l   = tid & 31;

    __shared__ __align__(16) float hred[9 * 256];
    __shared__ __align__(16) float sbuf[256];
    __shared__ __align__(16) float fbuf[256];
    __shared__ float hobuf[256];

    const int sym = sym_ids[n];
    const size_t sk_stride = (size_t)M_GEMM * N_GEMM;

    // ---- Phase 0: split-K reduce for this roi's 9x256 block ----
    #pragma unroll
    for (int v = tid; v < 9 * 256; v += 1024) {
        const size_t off = (size_t)(n * 9) * N_GEMM + v;
        float s = 0.0f;
        #pragma unroll
        for (int sp = 0; sp < SPLITK; sp++)
            s += g_hpart[(size_t)sp * sk_stride + off];
        hred[v] = s;
    }
    __syncthreads();

    // ---- Phase 1: GN + relu + spatial mean (threads 0..255; warp == group) ----
    if (tid < 256) {
        const int e = tid;
        float hvp[9];
        #pragma unroll
        for (int p = 0; p < 9; p++)
            hvp[p] = hred[p * 256 + e];

        float lsum = 0.0f;
        #pragma unroll
        for (int p = 0; p < 9; p++) lsum += hvp[p];
        #pragma unroll
        for (int o = 16; o > 0; o >>= 1) lsum += __shfl_xor_sync(0xffffffffu, lsum, o);
        const float mean = lsum * (1.0f / 288.0f);

        float lsq = 0.0f;
        #pragma unroll
        for (int p = 0; p < 9; p++) { float d = hvp[p] - mean; lsq += d * d; }
        #pragma unroll
        for (int o = 16; o > 0; o >>= 1) lsq += __shfl_xor_sync(0xffffffffu, lsq, o);
        const float inv = rsqrtf(lsq * (1.0f / 288.0f) + 1e-5f);

        const float sc = gn_scale[e];
        const float bi = gn_bias[e];
        float acc = 0.0f;
        #pragma unroll
        for (int p = 0; p < 9; p++)
            acc += fmaxf((hvp[p] - mean) * inv * sc + bi, 0.0f);
        sbuf[e] = acc * (1.0f / 9.0f);
    }
    __syncthreads();

    // ---- Phase 2: head GEMV (warp w -> outputs w*8..w*8+7, float4 loads) ----
    {
        const float4 sva = *(const float4*)&sbuf[l * 4];
        const float4 svb = *(const float4*)&sbuf[128 + l * 4];

        float a[8];
        #pragma unroll
        for (int o = 0; o < 8; o++) {
            const float* __restrict__ row = head_w + (size_t)(w * 8 + o) * 256;
            const float4 wa = *(const float4*)(row + l * 4);
            const float4 wb = *(const float4*)(row + 128 + l * 4);
            float t = sva.x * wa.x + sva.y * wa.y + sva.z * wa.z + sva.w * wa.w;
            t = fmaf(svb.x, wb.x, t); t = fmaf(svb.y, wb.y, t);
            t = fmaf(svb.z, wb.z, t); t = fmaf(svb.w, wb.w, t);
            a[o] = t;
        }
        #pragma unroll
        for (int o = 0; o < 8; o++) {
            #pragma unroll
            for (int off = 16; off > 0; off >>= 1)
                a[o] += __shfl_xor_sync(0xffffffffu, a[o], off);
        }
        if (l < 8) {
            const int e = w * 8 + l;
            float v = a[0];
            #pragma unroll
            for (int o = 1; o < 8; o++) v = (l == o) ? a[o] : v;
            hobuf[e] = v + head_b[e];
        }
    }
    __syncthreads();

    // ---- fused vector (threads 0..255) ----
    if (tid < 256) {
        const int e = tid;
        const float ho = fmaxf(hobuf[e], 0.0f);
        const float b0 = boxes[n*4+0], b1 = boxes[n*4+1],
                    b2 = boxes[n*4+2], b3 = boxes[n*4+3];
        float sp = spat_b[e] + b0 * spat_w[e*4+0] + b1 * spat_w[e*4+1]
                             + b2 * spat_w[e*4+2] + b3 * spat_w[e*4+3];
        sp = fmaxf(sp, 0.0f);
        fbuf[e] = ho + sp + sym_emb[sym * 256 + e];
    }
    __syncthreads();

    // ---- Phase 3: fuse GEMV ----
    {
        const float4 fva = *(const float4*)&fbuf[l * 4];
        const float4 fvb = *(const float4*)&fbuf[128 + l * 4];

        float a[8];
        #pragma unroll
        for (int o = 0; o < 8; o++) {
            const float* __restrict__ row =
                fuse_w + ((size_t)sym * 256 + (size_t)(w * 8 + o)) * 256;
            const float4 wa = *(const float4*)(row + l * 4);
            const float4 wb = *(const float4*)(row + 128 + l * 4);
            float t = fva.x * wa.x + fva.y * wa.y + fva.z * wa.z + fva.w * wa.w;
            t = fmaf(fvb.x, wb.x, t); t = fmaf(fvb.y, wb.y, t);
            t = fmaf(fvb.z, wb.z, t); t = fmaf(fvb.w, wb.w, t);
            a[o] = t;
        }
        #pragma unroll
        for (int o = 0; o < 8; o++) {
            #pragma unroll
            for (int off = 16; off > 0; off >>= 1)
                a[o] += __shfl_xor_sync(0xffffffffu, a[o], off);
        }
        if (l < 8) {
            const int e = w * 8 + l;
            float v = a[0];
            #pragma unroll
            for (int o = 1; o < 8; o++) v = (l == o) ? a[o] : v;
            out[(size_t)n * 256 + e] = fmaxf(v + fuse_b[sym * 256 + e], 0.0f);
        }
    }
}

// ---------------------------------------------------------------------------
extern "C" void kernel_launch(void* const* d_in, const int* in_sizes, int n_in,
                              void* d_out, int out_size)
{
    const float* fm        = (const float*)d_in[0];
    const float* boxes     = (const float*)d_in[1];
    const float* conv_w    = (const float*)d_in[2];
    const float* gn_scale  = (const float*)d_in[3];
    const float* gn_bias   = (const float*)d_in[4];
    const float* head_w    = (const float*)d_in[5];
    const float* head_b    = (const float*)d_in[6];
    const float* spat_w    = (const float*)d_in[7];
    const float* spat_b    = (const float*)d_in[8];
    const float* sym_emb   = (const float*)d_in[9];
    const float* fuse_w    = (const float*)d_in[10];
    const float* fuse_b    = (const float*)d_in[11];
    const int*   batch_idx = (const int*)d_in[12];
    const int*   level_idx = (const int*)d_in[13];
    const int*   sym_ids   = (const int*)d_in[14];
    float* out = (float*)d_out;

    cudaFuncSetAttribute(k_gemm_mma,
                         cudaFuncAttributeMaxDynamicSharedMemorySize, GEMM_SMEM_BYTES);

    dim3 g1(NROI, 9);
    k_roi<<<g1, 256>>>(fm, boxes, batch_idx, level_idx);

    dim3 g2(M_GEMM / 128, N_GEMM / 128, SPLITK);   // (9, 2, 8) = 144 CTAs
    k_gemm_mma<<<g2, 256, GEMM_SMEM_BYTES>>>(conv_w);

    k_epilogue<<<NROI, 1024>>>(boxes, gn_scale, gn_bias, head_w, head_b,
                               spat_w, spat_b, sym_emb, fuse_w, fuse_b,
                               sym_ids, out);
}